// round 15
// baseline (speedup 1.0000x reference)
#include <cuda_runtime.h>
#include <cuda_bf16.h>
#include <cuda_fp16.h>
#include <math.h>
#include <stdint.h>

// Model dims
#define BB 4
#define SS 1024
#define VV 32000
#define DD 1024
#define HH 16
#define HD 64
#define LL 8
#define FF_DIM 4096
#define NTOK (BB * SS)   // 4096

// Weight element counts / offsets inside the fp16 weight buffer
#define NQKV   25165824
#define NPROJ  8388608
#define NW1    33554432
#define NW2    33554432
#define NHEAD  32768000
#define OFF_QKV  0
#define OFF_PROJ 25165824
#define OFF_W1   33554432
#define OFF_W2   67108864
#define OFF_HEAD 100663296
#define TOTW     133431296

// stage: Ah 16KB + Al 16KB + B 16KB = 48KB; 2 stages = 96KB (2 CTAs/SM)
#define STAGE_BYTES 49152
#define SMEM_GEMM (1024 + 2 * STAGE_BYTES)

// ---------------- scratch (device globals; no allocation) ----------------
__device__ float g_x[NTOK * DD];          // residual stream (fp32)
__device__ __half g_qkvh[NTOK * 3 * DD];  // qkv projection (fp16, attn input)
__device__ __half g_lnh[NTOK * DD], g_lnl[NTOK * DD];
__device__ __half g_ah [NTOK * DD], g_al [NTOK * DD];
__device__ __half g_ffh[NTOK * FF_DIM], g_ffl[NTOK * FF_DIM];
__device__ __half g_w[TOTW];              // all weights, single fp16

// ---------------- PTX helpers (baseline ISA only) ----------------
__device__ __forceinline__ uint32_t smem_u32(const void* p) {
    uint32_t a;
    asm("{ .reg .u64 t; cvta.to.shared.u64 t, %1; cvt.u32.u64 %0, t; }" : "=r"(a) : "l"(p));
    return a;
}
__device__ __forceinline__ void cp16(uint32_t s, const void* g) {
    asm volatile("cp.async.cg.shared.global [%0], [%1], 16;" :: "r"(s), "l"(g) : "memory");
}
__device__ __forceinline__ void cp_commit() { asm volatile("cp.async.commit_group;" ::: "memory"); }
__device__ __forceinline__ void cp_wait0()  { asm volatile("cp.async.wait_group 0;" ::: "memory"); }
__device__ __forceinline__ void cp_wait1()  { asm volatile("cp.async.wait_group 1;" ::: "memory"); }

__device__ __forceinline__ void ldsm4(uint32_t addr, uint32_t* r) {
    asm volatile("ldmatrix.sync.aligned.m8n8.x4.shared.b16 {%0,%1,%2,%3}, [%4];"
        : "=r"(r[0]), "=r"(r[1]), "=r"(r[2]), "=r"(r[3]) : "r"(addr));
}
__device__ __forceinline__ void ldsm4t(uint32_t addr, uint32_t* r) {
    asm volatile("ldmatrix.sync.aligned.m8n8.x4.trans.shared.b16 {%0,%1,%2,%3}, [%4];"
        : "=r"(r[0]), "=r"(r[1]), "=r"(r[2]), "=r"(r[3]) : "r"(addr));
}
__device__ __forceinline__ void mma_f16(float* c, const uint32_t* a, uint32_t b0, uint32_t b1) {
    asm volatile(
        "mma.sync.aligned.m16n8k16.row.col.f32.f16.f16.f32 "
        "{%0,%1,%2,%3}, {%4,%5,%6,%7}, {%8,%9}, {%0,%1,%2,%3};"
        : "+f"(c[0]), "+f"(c[1]), "+f"(c[2]), "+f"(c[3])
        : "r"(a[0]), "r"(a[1]), "r"(a[2]), "r"(a[3]), "r"(b0), "r"(b1));
}
__device__ __forceinline__ uint32_t swz(uint32_t off) { return off ^ ((off >> 3) & 0x70); }

__device__ __forceinline__ uint32_t pk2h(float a, float b) {
    __half2 h = __floats2half2_rn(a, b);
    return *(uint32_t*)&h;
}

// ---------------- fused weight round: fp32 -> single fp16, all 5 tensors ----------------
__global__ __launch_bounds__(256) void split_all_kernel(
    const float4* __restrict__ qkv_w, const float4* __restrict__ proj_w,
    const float4* __restrict__ w1, const float4* __restrict__ w2,
    const float4* __restrict__ head_w, uint2* __restrict__ out)
{
    long i = (long)blockIdx.x * 256 + threadIdx.x;   // unit = 4 floats
    if (i >= (long)(TOTW / 4)) return;
    const float4* src;
    long off;
    if (i < (long)(OFF_PROJ / 4))      { src = qkv_w;  off = i; }
    else if (i < (long)(OFF_W1 / 4))   { src = proj_w; off = i - OFF_PROJ / 4; }
    else if (i < (long)(OFF_W2 / 4))   { src = w1;     off = i - OFF_W1 / 4; }
    else if (i < (long)(OFF_HEAD / 4)) { src = w2;     off = i - OFF_W2 / 4; }
    else                               { src = head_w; off = i - OFF_HEAD / 4; }
    float4 v = src[off];
    uint2 hv;
    hv.x = pk2h(v.x, v.y); hv.y = pk2h(v.z, v.w);
    out[i] = hv;
}

// ---------------- embedding ----------------
__global__ __launch_bounds__(256) void embed_kernel(
    const int* __restrict__ idx, const float* __restrict__ tok,
    const float* __restrict__ pos, float* __restrict__ x)
{
    int t = blockIdx.x;
    int s = t & (SS - 1);
    int token = idx[t];
    const float4* te = (const float4*)(tok + (size_t)token * DD);
    const float4* pe = (const float4*)(pos + (size_t)s * DD);
    float4* xr = (float4*)(x + (size_t)t * DD);
    int d = threadIdx.x;
    float4 a = te[d], b = pe[d];
    xr[d] = make_float4(a.x + b.x, a.y + b.y, a.z + b.z, a.w + b.w);
}

// ---------------- layernorm -> split fp16 hi/lo ----------------
__global__ __launch_bounds__(256) void ln_kernel(
    const float* __restrict__ x, const float* __restrict__ gw,
    const float* __restrict__ bw, __half* __restrict__ yh,
    __half* __restrict__ yl)
{
    __shared__ float rs[8], rq[8];
    int row = blockIdx.x;
    const float4* xr = (const float4*)(x + (size_t)row * DD);
    float4 v = xr[threadIdx.x];
    float sum = v.x + v.y + v.z + v.w;
    float sq = v.x * v.x + v.y * v.y + v.z * v.z + v.w * v.w;
#pragma unroll
    for (int o = 16; o; o >>= 1) {
        sum += __shfl_xor_sync(0xffffffffu, sum, o);
        sq  += __shfl_xor_sync(0xffffffffu, sq, o);
    }
    int warp = threadIdx.x >> 5;
    if ((threadIdx.x & 31) == 0) { rs[warp] = sum; rq[warp] = sq; }
    __syncthreads();
    float ts = 0.f, tq = 0.f;
#pragma unroll
    for (int w = 0; w < 8; w++) { ts += rs[w]; tq += rq[w]; }
    float mu = ts * (1.f / DD);
    float var = tq * (1.f / DD) - mu * mu;
    float inv = rsqrtf(var + 1e-5f);
    float4 g = ((const float4*)gw)[threadIdx.x];
    float4 bb = ((const float4*)bw)[threadIdx.x];
    float y0 = (v.x - mu) * inv * g.x + bb.x;
    float y1 = (v.y - mu) * inv * g.y + bb.y;
    float y2 = (v.z - mu) * inv * g.z + bb.z;
    float y3 = (v.w - mu) * inv * g.w + bb.w;
    __half h0 = __float2half_rn(y0), h1 = __float2half_rn(y1);
    __half h2 = __float2half_rn(y2), h3 = __float2half_rn(y3);
    uint2 hv, lv;
    hv.x = (uint32_t)__half_as_ushort(h0) | ((uint32_t)__half_as_ushort(h1) << 16);
    hv.y = (uint32_t)__half_as_ushort(h2) | ((uint32_t)__half_as_ushort(h3) << 16);
    lv.x = pk2h(y0 - __half2float(h0), y1 - __half2float(h1));
    lv.y = pk2h(y2 - __half2float(h2), y3 - __half2float(h3));
    ((uint2*)(yh + (size_t)row * DD))[threadIdx.x] = hv;
    ((uint2*)(yl + (size_t)row * DD))[threadIdx.x] = lv;
}

// ---------------- fp16 2-pass mma.sync GEMM (K, N compile-time) ----------------
// C[M,N] = (Ah+Al)[M,K] @ B[N,K]^T   (A fp16 hi/lo, B single fp16)
// CTA tile 128x128, BK=64, 8 warps (2m x 4n), warp tile 64x32, 2 CTAs/SM.
template<int K, int N>
__global__ __launch_bounds__(256, 2) void gemm_tc(
    const __half* __restrict__ Ah, const __half* __restrict__ Al,
    const __half* __restrict__ B,
    const float* __restrict__ bias, const float* __restrict__ res,
    float* __restrict__ Cf, __half* __restrict__ Cs,
    __half* __restrict__ Chh, __half* __restrict__ Cll,
    int silu)
{
    extern __shared__ char smem[];
    const int tid = threadIdx.x;
    const int wid = tid >> 5;
    const int lane = tid & 31;
    const int m0 = blockIdx.x * 128;
    const int n0 = blockIdx.y * 128;
    const int wm = wid & 1;
    const int wn = wid >> 1;

    uint32_t sbase = smem_u32(smem);
    uint32_t tiles = (sbase + 1023) & ~1023u;
    // stage: Ah @0 (16KB), Al @16K (16KB), B @32K (16KB)

    uint32_t swo[4];
    const char *gA[4], *gAl[4], *gB[4];
#pragma unroll
    for (int u = 0; u < 4; u++) {
        int unit = tid + u * 256;
        int row = unit >> 3;
        int cb = (unit & 7) * 16;
        swo[u] = swz((uint32_t)(row * 128 + cb));
        gA[u]  = (const char*)Ah + ((size_t)(m0 + row) * K) * 2 + cb;
        gAl[u] = (const char*)Al + ((size_t)(m0 + row) * K) * 2 + cb;
        gB[u]  = (const char*)B + ((size_t)(n0 + row) * K) * 2 + cb;
    }

    const int lr8  = lane & 7;
    const int radd = ((lane >> 3) & 1) * 8;
    const int cadd = (lane >> 4) * 16;
    const int arow = wm * 64 + lr8 + radd;
    const int brow = wn * 32 + lr8 + radd;

    // swizzle-free ldsm addressing (mi*16 keeps row&7 invariant)
    const uint32_t abase = (uint32_t)arow * 128;
    const uint32_t xa = (uint32_t)((arow & 7) * 16);
    const uint32_t bbase = (uint32_t)brow * 128;
    const uint32_t xb = (uint32_t)((brow & 7) * 16);

    float acc[64];
#pragma unroll
    for (int i = 0; i < 64; i++) acc[i] = 0.f;

    constexpr int nk = K >> 6;

    {
        uint32_t st = tiles;
#pragma unroll
        for (int u = 0; u < 4; u++) {
            cp16(st + swo[u],         gA[u]);
            cp16(st + 16384 + swo[u], gAl[u]);
            cp16(st + 32768 + swo[u], gB[u]);
        }
        cp_commit(); cp_wait0();
    }
    __syncthreads();

#pragma unroll 1
    for (int kc = 0; kc < nk; kc++) {
        int b = kc & 1;
        uint32_t st = tiles + (uint32_t)b * STAGE_BYTES;

        if (kc + 1 < nk) {
            uint32_t st2 = tiles + (uint32_t)(b ^ 1) * STAGE_BYTES;
            uint32_t koff = (uint32_t)(kc + 1) * 128;
#pragma unroll
            for (int u = 0; u < 4; u++) {
                cp16(st2 + swo[u],         gA[u] + koff);
                cp16(st2 + 16384 + swo[u], gAl[u] + koff);
                cp16(st2 + 32768 + swo[u], gB[u] + koff);
            }
            cp_commit();
        }

        const uint32_t stA = st, stAl = st + 16384, stB = st + 32768;
#pragma unroll
        for (int ks = 0; ks < 4; ks++) {
            const uint32_t cbk = (uint32_t)(ks * 32) + (uint32_t)cadd;
            const uint32_t ca = abase + (cbk ^ xa);   // + mi*2048 per A frag
            const uint32_t cbb = bbase + (cbk ^ xb);  // + n2*2048 per B frag

            uint32_t bf[2][4];
            ldsm4(stB + cbb, bf[0]);
            ldsm4(stB + cbb + 2048, bf[1]);

            // mi pair 0 (mi = 0,1)
            uint32_t ah0[4], ah1[4], al0[4], al1[4];
            ldsm4(stA + ca, ah0);
            ldsm4(stA + ca + 2048, ah1);
            ldsm4(stAl + ca, al0);
            ldsm4(stAl + ca + 2048, al1);
#pragma unroll
            for (int ni = 0; ni < 4; ni++) {
                uint32_t b0 = bf[ni >> 1][ni & 1], b1 = bf[ni >> 1][(ni & 1) + 2];
                mma_f16(&acc[(0 * 4 + ni) * 4], ah0, b0, b1);
                mma_f16(&acc[(1 * 4 + ni) * 4], ah1, b0, b1);
                mma_f16(&acc[(0 * 4 + ni) * 4], al0, b0, b1);
                mma_f16(&acc[(1 * 4 + ni) * 4], al1, b0, b1);
            }

            // mi pair 1 (mi = 2,3)
            ldsm4(stA + ca + 4096, ah0);
            ldsm4(stA + ca + 6144, ah1);
            ldsm4(stAl + ca + 4096, al0);
            ldsm4(stAl + ca + 6144, al1);
#pragma unroll
            for (int ni = 0; ni < 4; ni++) {
                uint32_t b0 = bf[ni >> 1][ni & 1], b1 = bf[ni >> 1][(ni & 1) + 2];
                mma_f16(&acc[(2 * 4 + ni) * 4], ah0, b0, b1);
                mma_f16(&acc[(3 * 4 + ni) * 4], ah1, b0, b1);
                mma_f16(&acc[(2 * 4 + ni) * 4], al0, b0, b1);
                mma_f16(&acc[(3 * 4 + ni) * 4], al1, b0, b1);
            }
        }

        if (kc + 1 < nk) cp_wait0();
        __syncthreads();
    }

    // ---------------- epilogue ----------------
    const int r  = lane >> 2;
    const int c2 = (lane & 3) * 2;
#pragma unroll
    for (int mi = 0; mi < 4; mi++) {
#pragma unroll
        for (int ni = 0; ni < 4; ni++) {
            float* cc = &acc[(mi * 4 + ni) * 4];
            int col = n0 + wn * 32 + ni * 8 + c2;
#pragma unroll
            for (int half = 0; half < 2; half++) {
                int m = m0 + wm * 64 + mi * 16 + r + half * 8;
                float v0 = cc[half * 2], v1 = cc[half * 2 + 1];
                if (bias) { v0 += bias[col]; v1 += bias[col + 1]; }
                if (silu) {
                    v0 = v0 / (1.f + __expf(-v0));
                    v1 = v1 / (1.f + __expf(-v1));
                }
                if (res) {
                    v0 += res[(size_t)m * N + col];
                    v1 += res[(size_t)m * N + col + 1];
                }
                if (Cf) *(float2*)(Cf + (size_t)m * N + col) = make_float2(v0, v1);
                if (Cs) *(uint32_t*)(Cs + (size_t)m * N + col) = pk2h(v0, v1);
                if (Chh) {
                    __half h0 = __float2half_rn(v0);
                    __half h1 = __float2half_rn(v1);
                    *(uint32_t*)(Chh + (size_t)m * N + col) =
                        (uint32_t)__half_as_ushort(h0) | ((uint32_t)__half_as_ushort(h1) << 16);
                    *(uint32_t*)(Cll + (size_t)m * N + col) =
                        pk2h(v0 - __half2float(h0), v1 - __half2float(h1));
                }
            }
        }
    }
}

// ---------------- HMMA fp16 flash attention (double-buffered K/V) ----------------
__global__ __launch_bounds__(128) void attn_hmma(
    const __half* __restrict__ qkvh,
    __half* __restrict__ oh, __half* __restrict__ ol)
{
    __shared__ __align__(128) char smem[40960];  // Q 8KB | K0 8KB | V0 8KB | K1 8KB | V1 8KB
    uint32_t sb = smem_u32(smem);
    const uint32_t qs = sb;

    const int qt = (int)gridDim.x - 1 - (int)blockIdx.x;   // reversed: long CTAs first
    const int h  = blockIdx.y;
    const int b  = blockIdx.z;
    const int tid = threadIdx.x;
    const int warp = tid >> 5;
    const int lane = tid & 31;

    const __half2 qscale = __floats2half2_rn(0.125f, 0.125f);
    for (int idx = tid; idx < 1024; idx += 128) {
        int row = idx >> 4, c4 = (idx & 15) * 4;
        const __half* p = qkvh + (size_t)(b * SS + qt * 64 + row) * (3 * DD) + h * 192 + c4;
        uint2 v = *(const uint2*)p;
        __half2* vh = (__half2*)&v;
        vh[0] = __hmul2(vh[0], qscale);
        vh[1] = __hmul2(vh[1], qscale);
        *(uint2*)(smem + swz((uint32_t)(row * 128 + c4 * 2))) = v;
    }

    auto load_kv = [&](int kt, int stg) {
        uint32_t kd = sb + 8192 + (uint32_t)stg * 16384;
        uint32_t vd = kd + 8192;
#pragma unroll
        for (int u = 0; u < 4; u++) {
            int unit = tid + u * 128;
            int row = unit >> 3;
            int cb = (unit & 7) * 16;
            const char* src = (const char*)(qkvh + (size_t)(b * SS + kt * 64 + row) * (3 * DD) + h * 192);
            uint32_t so = swz((uint32_t)(row * 128 + cb));
            cp16(kd + so, src + 128 + cb);
            cp16(vd + so, src + 256 + cb);
        }
        cp_commit();
    };

    load_kv(0, 0);

    const int lr8  = lane & 7;
    const int radd = ((lane >> 3) & 1) * 8;
    const int cadd = (lane >> 4) * 16;
    const int arow = warp * 16 + lr8 + radd;

    __syncthreads();
    uint32_t qa[4][4];
#pragma unroll
    for (int kk = 0; kk < 4; kk++)
        ldsm4(qs + swz((uint32_t)(arow * 128 + kk * 32 + cadd)), qa[kk]);

    float o[8][4];
#pragma unroll
    for (int f = 0; f < 8; f++)
#pragma unroll
        for (int j = 0; j < 4; j++) o[f][j] = 0.f;
    float m0v = -1e30f, m1v = -1e30f, l0 = 0.f, l1 = 0.f;
    const int rq0 = qt * 64 + warp * 16 + (lane >> 2);

    for (int kt = 0; kt <= qt; kt++) {
        int stg = kt & 1;
        if (kt < qt) { load_kv(kt + 1, stg ^ 1); cp_wait1(); }
        else cp_wait0();
        __syncthreads();
        const uint32_t ks = sb + 8192 + (uint32_t)stg * 16384;
        const uint32_t vs = ks + 8192;

        float s[8][4];
#pragma unroll
        for (int f = 0; f < 8; f++)
#pragma unroll
            for (int j = 0; j < 4; j++) s[f][j] = 0.f;
#pragma unroll
        for (int kk = 0; kk < 4; kk++) {
            int cb = kk * 32 + cadd;
            uint32_t bf[4][4];
#pragma unroll
            for (int n2 = 0; n2 < 4; n2++)
                ldsm4(ks + swz((uint32_t)((n2 * 16 + lr8 + radd) * 128 + cb)), bf[n2]);
#pragma unroll
            for (int ni = 0; ni < 8; ni++)
                mma_f16(s[ni], qa[kk], bf[ni >> 1][ni & 1], bf[ni >> 1][(ni & 1) + 2]);
        }

        if (kt == qt) {
#pragma unroll
            for (int f = 0; f < 8; f++)
#pragma unroll
                for (int j = 0; j < 4; j++) {
                    int kc = kt * 64 + f * 8 + (lane & 3) * 2 + (j & 1);
                    int rr = rq0 + ((j >= 2) ? 8 : 0);
                    if (kc > rr) s[f][j] = -1e30f;
                }
        }

        float tm0 = -1e30f, tm1 = -1e30f;
#pragma unroll
        for (int f = 0; f < 8; f++) {
            tm0 = fmaxf(tm0, fmaxf(s[f][0], s[f][1]));
            tm1 = fmaxf(tm1, fmaxf(s[f][2], s[f][3]));
        }
        tm0 = fmaxf(tm0, __shfl_xor_sync(0xffffffffu, tm0, 1));
        tm0 = fmaxf(tm0, __shfl_xor_sync(0xffffffffu, tm0, 2));
        tm1 = fmaxf(tm1, __shfl_xor_sync(0xffffffffu, tm1, 1));
        tm1 = fmaxf(tm1, __shfl_xor_sync(0xffffffffu, tm1, 2));
        float nm0 = fmaxf(m0v, tm0), nm1 = fmaxf(m1v, tm1);
        float f0 = __expf(m0v - nm0), f1 = __expf(m1v - nm1);
        float ts0 = 0.f, ts1 = 0.f;
#pragma unroll
        for (int f = 0; f < 8; f++) {
            s[f][0] = __expf(s[f][0] - nm0);
            s[f][1] = __expf(s[f][1] - nm0);
            s[f][2] = __expf(s[f][2] - nm1);
            s[f][3] = __expf(s[f][3] - nm1);
            ts0 += s[f][0] + s[f][1];
            ts1 += s[f][2] + s[f][3];
        }
        ts0 += __shfl_xor_sync(0xffffffffu, ts0, 1);
        ts0 += __shfl_xor_sync(0xffffffffu, ts0, 2);
        ts1 += __shfl_xor_sync(0xffffffffu, ts1, 1);
        ts1 += __shfl_xor_sync(0xffffffffu, ts1, 2);
        l0 = l0 * f0 + ts0; l1 = l1 * f1 + ts1;
        m0v = nm0; m1v = nm1;
#pragma unroll
        for (int f = 0; f < 8; f++) {
            o[f][0] *= f0; o[f][1] *= f0; o[f][2] *= f1; o[f][3] *= f1;
        }

        uint32_t pa[4][4];
#pragma unroll
        for (int kk = 0; kk < 4; kk++) {
            pa[kk][0] = pk2h(s[2 * kk][0],     s[2 * kk][1]);
            pa[kk][1] = pk2h(s[2 * kk][2],     s[2 * kk][3]);
            pa[kk][2] = pk2h(s[2 * kk + 1][0], s[2 * kk + 1][1]);
            pa[kk][3] = pk2h(s[2 * kk + 1][2], s[2 * kk + 1][3]);
        }
#pragma unroll
        for (int kk = 0; kk < 4; kk++) {
            uint32_t vbf[4][4];
#pragma unroll
            for (int ng = 0; ng < 4; ng++)
                ldsm4t(vs + swz((uint32_t)((kk * 16 + lr8 + radd) * 128 + ng * 32 + cadd)), vbf[ng]);
#pragma unroll
            for (int ni = 0; ni < 8; ni++)
                mma_f16(o[ni], pa[kk], vbf[ni >> 1][(ni & 1) * 2], vbf[ni >> 1][(ni & 1) * 2 + 1]);
        }
        __syncthreads();
    }

    float il0 = 1.f / l0, il1 = 1.f / l1;
    const int row0 = b * SS + rq0;
#pragma unroll
    for (int f = 0; f < 8; f++) {
        int col = h * 64 + f * 8 + (lane & 3) * 2;
        float v0 = o[f][0] * il0, v1 = o[f][1] * il0;
        float v2 = o[f][2] * il1, v3 = o[f][3] * il1;
        __half h0 = __float2half_rn(v0), h1 = __float2half_rn(v1);
        __half h2 = __float2half_rn(v2), h3 = __float2half_rn(v3);
        size_t p0 = (size_t)row0 * DD + col;
        size_t p1 = (size_t)(row0 + 8) * DD + col;
        *(uint32_t*)(oh + p0) = (uint32_t)__half_as_ushort(h0) | ((uint32_t)__half_as_ushort(h1) << 16);
        *(uint32_t*)(ol + p0) = pk2h(v0 - __half2float(h0), v1 - __half2float(h1));
        *(uint32_t*)(oh + p1) = (uint32_t)__half_as_ushort(h2) | ((uint32_t)__half_as_ushort(h3) << 16);
        *(uint32_t*)(ol + p1) = pk2h(v2 - __half2float(h2), v3 - __half2float(h3));
    }
}

// ---------------- launch ----------------
extern "C" void kernel_launch(void* const* d_in, const int* in_sizes, int n_in,
                              void* d_out, int out_size)
{
    const int*   idx     = (const int*)d_in[0];
    const float* tok_emb = (const float*)d_in[1];
    const float* pos_emb = (const float*)d_in[2];
    const float* qkv_w   = (const float*)d_in[3];
    const float* proj_w  = (const float*)d_in[4];
    const float* proj_b  = (const float*)d_in[5];
    const float* ln1_g   = (const float*)d_in[6];
    const float* ln1_b   = (const float*)d_in[7];
    const float* ln2_g   = (const float*)d_in[8];
    const float* ln2_b   = (const float*)d_in[9];
    const float* w1      = (const float*)d_in[10];
    const float* b1      = (const float*)d_in[11];
    const float* w2      = (const float*)d_in[12];
    const float* b2      = (const float*)d_in[13];
    const float* lnf_g   = (const float*)d_in[14];
    const float* lnf_b   = (const float*)d_in[15];
    const float* head_w  = (const float*)d_in[16];
    const float* head_b  = (const float*)d_in[17];
    float* out = (float*)d_out;

    float* x;
    __half *qkvh, *lnh, *lnl, *ah, *al, *ffh, *ffl, *w;
    cudaGetSymbolAddress((void**)&x, g_x);
    cudaGetSymbolAddress((void**)&qkvh, g_qkvh);
    cudaGetSymbolAddress((void**)&lnh, g_lnh);
    cudaGetSymbolAddress((void**)&lnl, g_lnl);
    cudaGetSymbolAddress((void**)&ah, g_ah);
    cudaGetSymbolAddress((void**)&al, g_al);
    cudaGetSymbolAddress((void**)&ffh, g_ffh);
    cudaGetSymbolAddress((void**)&ffl, g_ffl);
    cudaGetSymbolAddress((void**)&w, g_w);

    cudaFuncSetAttribute(gemm_tc<1024, 3072>,  cudaFuncAttributeMaxDynamicSharedMemorySize, SMEM_GEMM);
    cudaFuncSetAttribute(gemm_tc<1024, 1024>,  cudaFuncAttributeMaxDynamicSharedMemorySize, SMEM_GEMM);
    cudaFuncSetAttribute(gemm_tc<1024, 4096>,  cudaFuncAttributeMaxDynamicSharedMemorySize, SMEM_GEMM);
    cudaFuncSetAttribute(gemm_tc<4096, 1024>,  cudaFuncAttributeMaxDynamicSharedMemorySize, SMEM_GEMM);
    cudaFuncSetAttribute(gemm_tc<1024, 32000>, cudaFuncAttributeMaxDynamicSharedMemorySize, SMEM_GEMM);

    // round all weights to single fp16 (one fused launch)
    split_all_kernel<<<(TOTW / 4 + 255) / 256, 256>>>(
        (const float4*)qkv_w, (const float4*)proj_w, (const float4*)w1,
        (const float4*)w2, (const float4*)head_w, (uint2*)w);

    embed_kernel<<<NTOK, 256>>>(idx, tok_emb, pos_emb, x);

    for (int l = 0; l < LL; l++) {
        // ln1 -> qkv (fp16 out for attention)
        ln_kernel<<<NTOK, 256>>>(x, ln1_g + l * DD, ln1_b + l * DD, lnh, lnl);
        gemm_tc<1024, 3072><<<dim3(32, 24), 256, SMEM_GEMM>>>(
            lnh, lnl, w + OFF_QKV + (size_t)l * 3 * DD * DD,
            nullptr, nullptr, nullptr, qkvh, nullptr, nullptr, 0);
        // attention (HMMA flash, double-buffered) -> split fp16 output
        attn_hmma<<<dim3(SS / 64, HH, BB), 128>>>(qkvh, ah, al);
        // proj + residual (fp32 x)
        gemm_tc<1024, 1024><<<dim3(32, 8), 256, SMEM_GEMM>>>(
            ah, al, w + OFF_PROJ + (size_t)l * DD * DD,
            proj_b + l * DD, x, x, nullptr, nullptr, nullptr, 0);
        // ln2 -> MLP
        ln_kernel<<<NTOK, 256>>>(x, ln2_g + l * DD, ln2_b + l * DD, lnh, lnl);
        gemm_tc<1024, 4096><<<dim3(32, 32), 256, SMEM_GEMM>>>(
            lnh, lnl, w + OFF_W1 + (size_t)l * FF_DIM * DD,
            b1 + l * FF_DIM, nullptr, nullptr, nullptr, ffh, ffl, 1);
        gemm_tc<4096, 1024><<<dim3(32, 8), 256, SMEM_GEMM>>>(
            ffh, ffl, w + OFF_W2 + (size_t)l * DD * FF_DIM,
            b2 + l * DD, x, x, nullptr, nullptr, nullptr, 0);
    }

    // final LN + LM head
    ln_kernel<<<NTOK, 256>>>(x, lnf_g, lnf_b, lnh, lnl);
    gemm_tc<1024, 32000><<<dim3(32, VV / 128), 256, SMEM_GEMM>>>(
        lnh, lnl, w + OFF_HEAD,
        head_b, nullptr, out, nullptr, nullptr, nullptr, 0);
}

// round 16
// speedup vs baseline: 1.0131x; 1.0131x over previous
#include <cuda_runtime.h>
#include <cuda_bf16.h>
#include <cuda_fp16.h>
#include <math.h>
#include <stdint.h>

// Model dims
#define BB 4
#define SS 1024
#define VV 32000
#define DD 1024
#define HH 16
#define HD 64
#define LL 8
#define FF_DIM 4096
#define NTOK (BB * SS)   // 4096

// Weight element counts / offsets inside the fp16 weight buffer
#define NQKV   25165824
#define NPROJ  8388608
#define NW1    33554432
#define NW2    33554432
#define NHEAD  32768000
#define OFF_QKV  0
#define OFF_PROJ 25165824
#define OFF_W1   33554432
#define OFF_W2   67108864
#define OFF_HEAD 100663296
#define TOTW     133431296

// stage: Ah 16KB + Al 16KB + B 16KB = 48KB; 2 stages = 96KB (2 CTAs/SM)
#define STAGE_BYTES 49152
#define SMEM_GEMM (1024 + 2 * STAGE_BYTES)

// ---------------- scratch (device globals; no allocation) ----------------
__device__ float g_x[NTOK * DD];          // residual stream (fp32)
__device__ __half g_qkvh[NTOK * 3 * DD];  // qkv projection (fp16, attn input)
__device__ __half g_lnh[NTOK * DD], g_lnl[NTOK * DD];
__device__ __half g_ah [NTOK * DD], g_al [NTOK * DD];
__device__ __half g_ffh[NTOK * FF_DIM], g_ffl[NTOK * FF_DIM];
__device__ __half g_w[TOTW];              // all weights, single fp16

// ---------------- PTX helpers (baseline ISA only) ----------------
__device__ __forceinline__ uint32_t smem_u32(const void* p) {
    uint32_t a;
    asm("{ .reg .u64 t; cvta.to.shared.u64 t, %1; cvt.u32.u64 %0, t; }" : "=r"(a) : "l"(p));
    return a;
}
__device__ __forceinline__ void cp16(uint32_t s, const void* g) {
    asm volatile("cp.async.cg.shared.global [%0], [%1], 16;" :: "r"(s), "l"(g) : "memory");
}
__device__ __forceinline__ void cp_commit() { asm volatile("cp.async.commit_group;" ::: "memory"); }
__device__ __forceinline__ void cp_wait0()  { asm volatile("cp.async.wait_group 0;" ::: "memory"); }
__device__ __forceinline__ void cp_wait1()  { asm volatile("cp.async.wait_group 1;" ::: "memory"); }

__device__ __forceinline__ void ldsm4(uint32_t addr, uint32_t* r) {
    asm volatile("ldmatrix.sync.aligned.m8n8.x4.shared.b16 {%0,%1,%2,%3}, [%4];"
        : "=r"(r[0]), "=r"(r[1]), "=r"(r[2]), "=r"(r[3]) : "r"(addr));
}
__device__ __forceinline__ void ldsm4t(uint32_t addr, uint32_t* r) {
    asm volatile("ldmatrix.sync.aligned.m8n8.x4.trans.shared.b16 {%0,%1,%2,%3}, [%4];"
        : "=r"(r[0]), "=r"(r[1]), "=r"(r[2]), "=r"(r[3]) : "r"(addr));
}
__device__ __forceinline__ void mma_f16(float* c, const uint32_t* a, uint32_t b0, uint32_t b1) {
    asm volatile(
        "mma.sync.aligned.m16n8k16.row.col.f32.f16.f16.f32 "
        "{%0,%1,%2,%3}, {%4,%5,%6,%7}, {%8,%9}, {%0,%1,%2,%3};"
        : "+f"(c[0]), "+f"(c[1]), "+f"(c[2]), "+f"(c[3])
        : "r"(a[0]), "r"(a[1]), "r"(a[2]), "r"(a[3]), "r"(b0), "r"(b1));
}
__device__ __forceinline__ uint32_t swz(uint32_t off) { return off ^ ((off >> 3) & 0x70); }

__device__ __forceinline__ uint32_t pk2h(float a, float b) {
    __half2 h = __floats2half2_rn(a, b);
    return *(uint32_t*)&h;
}

// ---------------- fused weight round: fp32 -> single fp16, all 5 tensors ----------------
__global__ __launch_bounds__(256) void split_all_kernel(
    const float4* __restrict__ qkv_w, const float4* __restrict__ proj_w,
    const float4* __restrict__ w1, const float4* __restrict__ w2,
    const float4* __restrict__ head_w, uint2* __restrict__ out)
{
    long i = (long)blockIdx.x * 256 + threadIdx.x;   // unit = 4 floats
    if (i >= (long)(TOTW / 4)) return;
    const float4* src;
    long off;
    if (i < (long)(OFF_PROJ / 4))      { src = qkv_w;  off = i; }
    else if (i < (long)(OFF_W1 / 4))   { src = proj_w; off = i - OFF_PROJ / 4; }
    else if (i < (long)(OFF_W2 / 4))   { src = w1;     off = i - OFF_W1 / 4; }
    else if (i < (long)(OFF_HEAD / 4)) { src = w2;     off = i - OFF_W2 / 4; }
    else                               { src = head_w; off = i - OFF_HEAD / 4; }
    float4 v = src[off];
    uint2 hv;
    hv.x = pk2h(v.x, v.y); hv.y = pk2h(v.z, v.w);
    out[i] = hv;
}

// ---------------- embedding ----------------
__global__ __launch_bounds__(256) void embed_kernel(
    const int* __restrict__ idx, const float* __restrict__ tok,
    const float* __restrict__ pos, float* __restrict__ x)
{
    int t = blockIdx.x;
    int s = t & (SS - 1);
    int token = idx[t];
    const float4* te = (const float4*)(tok + (size_t)token * DD);
    const float4* pe = (const float4*)(pos + (size_t)s * DD);
    float4* xr = (float4*)(x + (size_t)t * DD);
    int d = threadIdx.x;
    float4 a = te[d], b = pe[d];
    xr[d] = make_float4(a.x + b.x, a.y + b.y, a.z + b.z, a.w + b.w);
}

// ---------------- layernorm -> split fp16 hi/lo ----------------
__global__ __launch_bounds__(256) void ln_kernel(
    const float* __restrict__ x, const float* __restrict__ gw,
    const float* __restrict__ bw, __half* __restrict__ yh,
    __half* __restrict__ yl)
{
    __shared__ float rs[8], rq[8];
    int row = blockIdx.x;
    const float4* xr = (const float4*)(x + (size_t)row * DD);
    float4 v = xr[threadIdx.x];
    float sum = v.x + v.y + v.z + v.w;
    float sq = v.x * v.x + v.y * v.y + v.z * v.z + v.w * v.w;
#pragma unroll
    for (int o = 16; o; o >>= 1) {
        sum += __shfl_xor_sync(0xffffffffu, sum, o);
        sq  += __shfl_xor_sync(0xffffffffu, sq, o);
    }
    int warp = threadIdx.x >> 5;
    if ((threadIdx.x & 31) == 0) { rs[warp] = sum; rq[warp] = sq; }
    __syncthreads();
    float ts = 0.f, tq = 0.f;
#pragma unroll
    for (int w = 0; w < 8; w++) { ts += rs[w]; tq += rq[w]; }
    float mu = ts * (1.f / DD);
    float var = tq * (1.f / DD) - mu * mu;
    float inv = rsqrtf(var + 1e-5f);
    float4 g = ((const float4*)gw)[threadIdx.x];
    float4 bb = ((const float4*)bw)[threadIdx.x];
    float y0 = (v.x - mu) * inv * g.x + bb.x;
    float y1 = (v.y - mu) * inv * g.y + bb.y;
    float y2 = (v.z - mu) * inv * g.z + bb.z;
    float y3 = (v.w - mu) * inv * g.w + bb.w;
    __half h0 = __float2half_rn(y0), h1 = __float2half_rn(y1);
    __half h2 = __float2half_rn(y2), h3 = __float2half_rn(y3);
    uint2 hv, lv;
    hv.x = (uint32_t)__half_as_ushort(h0) | ((uint32_t)__half_as_ushort(h1) << 16);
    hv.y = (uint32_t)__half_as_ushort(h2) | ((uint32_t)__half_as_ushort(h3) << 16);
    lv.x = pk2h(y0 - __half2float(h0), y1 - __half2float(h1));
    lv.y = pk2h(y2 - __half2float(h2), y3 - __half2float(h3));
    ((uint2*)(yh + (size_t)row * DD))[threadIdx.x] = hv;
    ((uint2*)(yl + (size_t)row * DD))[threadIdx.x] = lv;
}

// ---------------- fp16 2-pass mma.sync GEMM (R14 version — frozen) ----------------
// C[M,N] = (Ah+Al)[M,K] @ B[N,K]^T   (A fp16 hi/lo, B single fp16)
// CTA tile 128x128, BK=64, 8 warps (2m x 4n), warp tile 64x32, 2 CTAs/SM.
__global__ __launch_bounds__(256, 2) void gemm_tc(
    const __half* __restrict__ Ah, const __half* __restrict__ Al,
    const __half* __restrict__ B,
    const float* __restrict__ bias, const float* __restrict__ res,
    float* __restrict__ Cf, __half* __restrict__ Cs,
    __half* __restrict__ Chh, __half* __restrict__ Cll,
    int M, int N, int K, int silu)
{
    extern __shared__ char smem[];
    const int tid = threadIdx.x;
    const int wid = tid >> 5;
    const int lane = tid & 31;
    const int m0 = blockIdx.x * 128;
    const int n0 = blockIdx.y * 128;
    const int wm = wid & 1;
    const int wn = wid >> 1;

    uint32_t sbase = smem_u32(smem);
    uint32_t tiles = (sbase + 1023) & ~1023u;
    // stage: Ah @0 (16KB), Al @16K (16KB), B @32K (16KB)

    uint32_t swo[4];
    const char *gA[4], *gAl[4], *gB[4];
#pragma unroll
    for (int u = 0; u < 4; u++) {
        int unit = tid + u * 256;
        int row = unit >> 3;
        int cb = (unit & 7) * 16;
        swo[u] = swz((uint32_t)(row * 128 + cb));
        gA[u]  = (const char*)Ah + ((size_t)(m0 + row) * K) * 2 + cb;
        gAl[u] = (const char*)Al + ((size_t)(m0 + row) * K) * 2 + cb;
        gB[u]  = (const char*)B + ((size_t)(n0 + row) * K) * 2 + cb;
    }

    const int lr8  = lane & 7;
    const int radd = ((lane >> 3) & 1) * 8;
    const int cadd = (lane >> 4) * 16;
    const int arow = wm * 64 + lr8 + radd;
    const int brow = wn * 32 + lr8 + radd;

    // swizzle-free ldsm addressing (mi*16 keeps row&7 invariant)
    const uint32_t abase = (uint32_t)arow * 128;
    const uint32_t xa = (uint32_t)((arow & 7) * 16);
    const uint32_t bbase = (uint32_t)brow * 128;
    const uint32_t xb = (uint32_t)((brow & 7) * 16);

    float acc[64];
#pragma unroll
    for (int i = 0; i < 64; i++) acc[i] = 0.f;

    const int nk = K >> 6;

    {
        uint32_t st = tiles;
#pragma unroll
        for (int u = 0; u < 4; u++) {
            cp16(st + swo[u],         gA[u]);
            cp16(st + 16384 + swo[u], gAl[u]);
            cp16(st + 32768 + swo[u], gB[u]);
        }
        cp_commit(); cp_wait0();
    }
    __syncthreads();

    for (int kc = 0; kc < nk; kc++) {
        int b = kc & 1;
        uint32_t st = tiles + (uint32_t)b * STAGE_BYTES;

        if (kc + 1 < nk) {
            uint32_t st2 = tiles + (uint32_t)(b ^ 1) * STAGE_BYTES;
            size_t koff = (size_t)(kc + 1) * 128;
#pragma unroll
            for (int u = 0; u < 4; u++) {
                cp16(st2 + swo[u],         gA[u] + koff);
                cp16(st2 + 16384 + swo[u], gAl[u] + koff);
                cp16(st2 + 32768 + swo[u], gB[u] + koff);
            }
            cp_commit();
        }

        const uint32_t stA = st, stAl = st + 16384, stB = st + 32768;
#pragma unroll
        for (int ks = 0; ks < 4; ks++) {
            const uint32_t cbk = (uint32_t)(ks * 32) + (uint32_t)cadd;
            const uint32_t ca = abase + (cbk ^ xa);   // + mi*2048 per A frag
            const uint32_t cbb = bbase + (cbk ^ xb);  // + n2*2048 per B frag

            uint32_t bf[2][4];
            ldsm4(stB + cbb, bf[0]);
            ldsm4(stB + cbb + 2048, bf[1]);

            // mi pair 0 (mi = 0,1)
            uint32_t ah0[4], ah1[4], al0[4], al1[4];
            ldsm4(stA + ca, ah0);
            ldsm4(stA + ca + 2048, ah1);
            ldsm4(stAl + ca, al0);
            ldsm4(stAl + ca + 2048, al1);
#pragma unroll
            for (int ni = 0; ni < 4; ni++) {
                uint32_t b0 = bf[ni >> 1][ni & 1], b1 = bf[ni >> 1][(ni & 1) + 2];
                mma_f16(&acc[(0 * 4 + ni) * 4], ah0, b0, b1);
                mma_f16(&acc[(1 * 4 + ni) * 4], ah1, b0, b1);
                mma_f16(&acc[(0 * 4 + ni) * 4], al0, b0, b1);
                mma_f16(&acc[(1 * 4 + ni) * 4], al1, b0, b1);
            }

            // mi pair 1 (mi = 2,3)
            ldsm4(stA + ca + 4096, ah0);
            ldsm4(stA + ca + 6144, ah1);
            ldsm4(stAl + ca + 4096, al0);
            ldsm4(stAl + ca + 6144, al1);
#pragma unroll
            for (int ni = 0; ni < 4; ni++) {
                uint32_t b0 = bf[ni >> 1][ni & 1], b1 = bf[ni >> 1][(ni & 1) + 2];
                mma_f16(&acc[(2 * 4 + ni) * 4], ah0, b0, b1);
                mma_f16(&acc[(3 * 4 + ni) * 4], ah1, b0, b1);
                mma_f16(&acc[(2 * 4 + ni) * 4], al0, b0, b1);
                mma_f16(&acc[(3 * 4 + ni) * 4], al1, b0, b1);
            }
        }

        if (kc + 1 < nk) cp_wait0();
        __syncthreads();
    }

    // ---------------- epilogue ----------------
    const int r  = lane >> 2;
    const int c2 = (lane & 3) * 2;
#pragma unroll
    for (int mi = 0; mi < 4; mi++) {
#pragma unroll
        for (int ni = 0; ni < 4; ni++) {
            float* cc = &acc[(mi * 4 + ni) * 4];
            int col = n0 + wn * 32 + ni * 8 + c2;
#pragma unroll
            for (int half = 0; half < 2; half++) {
                int m = m0 + wm * 64 + mi * 16 + r + half * 8;
                float v0 = cc[half * 2], v1 = cc[half * 2 + 1];
                if (bias) { v0 += bias[col]; v1 += bias[col + 1]; }
                if (silu) {
                    v0 = v0 / (1.f + __expf(-v0));
                    v1 = v1 / (1.f + __expf(-v1));
                }
                if (res) {
                    v0 += res[(size_t)m * N + col];
                    v1 += res[(size_t)m * N + col + 1];
                }
                if (Cf) *(float2*)(Cf + (size_t)m * N + col) = make_float2(v0, v1);
                if (Cs) *(uint32_t*)(Cs + (size_t)m * N + col) = pk2h(v0, v1);
                if (Chh) {
                    __half h0 = __float2half_rn(v0);
                    __half h1 = __float2half_rn(v1);
                    *(uint32_t*)(Chh + (size_t)m * N + col) =
                        (uint32_t)__half_as_ushort(h0) | ((uint32_t)__half_as_ushort(h1) << 16);
                    *(uint32_t*)(Cll + (size_t)m * N + col) =
                        pk2h(v0 - __half2float(h0), v1 - __half2float(h1));
                }
            }
        }
    }
}

// ---------------- HMMA fp16 flash attention, 128-query CTAs ----------------
// grid (S/128, H, B), 256 threads (8 warps). Warp w owns queries w*16..+15.
// 64-key K/V tiles double-buffered via cp.async; warps outside their causal
// range skip compute (barriers stay collective). qt reversed: long CTAs first.
__global__ __launch_bounds__(256) void attn_hmma(
    const __half* __restrict__ qkvh,
    __half* __restrict__ oh, __half* __restrict__ ol)
{
    __shared__ __align__(128) char smem[49152];  // Q 16KB | K0 8 | V0 8 | K1 8 | V1 8
    uint32_t sb = smem_u32(smem);
    const uint32_t qs = sb;

    const int qt = (int)gridDim.x - 1 - (int)blockIdx.x;   // 0..7, reversed
    const int h  = blockIdx.y;
    const int b  = blockIdx.z;
    const int tid = threadIdx.x;
    const int warp = tid >> 5;
    const int lane = tid & 31;

    // load Q tile: 128 rows (scaled by HD^-0.5 = 0.125, exact in fp16)
    const __half2 qscale = __floats2half2_rn(0.125f, 0.125f);
    for (int idx = tid; idx < 2048; idx += 256) {
        int row = idx >> 4, c4 = (idx & 15) * 4;
        const __half* p = qkvh + (size_t)(b * SS + qt * 128 + row) * (3 * DD) + h * 192 + c4;
        uint2 v = *(const uint2*)p;
        __half2* vh = (__half2*)&v;
        vh[0] = __hmul2(vh[0], qscale);
        vh[1] = __hmul2(vh[1], qscale);
        *(uint2*)(smem + swz((uint32_t)(row * 128 + c4 * 2))) = v;
    }

    // K/V tile loader: 512 16B-units per 8KB tile, 2 per thread
    auto load_kv = [&](int kt, int stg) {
        uint32_t kd = sb + 16384 + (uint32_t)stg * 16384;
        uint32_t vd = kd + 8192;
#pragma unroll
        for (int u = 0; u < 2; u++) {
            int unit = tid + u * 256;           // 0..511
            int row = unit >> 3;
            int cb = (unit & 7) * 16;
            const char* src = (const char*)(qkvh + (size_t)(b * SS + kt * 64 + row) * (3 * DD) + h * 192);
            uint32_t so = swz((uint32_t)(row * 128 + cb));
            cp16(kd + so, src + 128 + cb);
            cp16(vd + so, src + 256 + cb);
        }
        cp_commit();
    };

    load_kv(0, 0);

    const int lr8  = lane & 7;
    const int radd = ((lane >> 3) & 1) * 8;
    const int cadd = (lane >> 4) * 16;
    const int arow = warp * 16 + lr8 + radd;   // 0..127

    __syncthreads();
    uint32_t qa[4][4];
#pragma unroll
    for (int kk = 0; kk < 4; kk++)
        ldsm4(qs + swz((uint32_t)(arow * 128 + kk * 32 + cadd)), qa[kk]);

    float o[8][4];
#pragma unroll
    for (int f = 0; f < 8; f++)
#pragma unroll
        for (int j = 0; j < 4; j++) o[f][j] = 0.f;
    float m0v = -1e30f, m1v = -1e30f, l0 = 0.f, l1 = 0.f;
    const int rq0 = qt * 128 + warp * 16 + (lane >> 2);     // query row (c0,c1)
    const int wlast = qt * 128 + warp * 16 + 15;            // warp's last query
    const int nkt = 2 * qt + 2;                             // key tiles needed by CTA

    for (int kt = 0; kt < nkt; kt++) {
        int stg = kt & 1;
        if (kt + 1 < nkt) { load_kv(kt + 1, stg ^ 1); cp_wait1(); }
        else cp_wait0();
        __syncthreads();
        const uint32_t ks = sb + 16384 + (uint32_t)stg * 16384;
        const uint32_t vs = ks + 8192;

        const bool active = (kt * 64 <= wlast);
        if (active) {
            float s[8][4];
#pragma unroll
            for (int f = 0; f < 8; f++)
#pragma unroll
                for (int j = 0; j < 4; j++) s[f][j] = 0.f;
#pragma unroll
            for (int kk = 0; kk < 4; kk++) {
                int cb = kk * 32 + cadd;
                uint32_t bf[4][4];
#pragma unroll
                for (int n2 = 0; n2 < 4; n2++)
                    ldsm4(ks + swz((uint32_t)((n2 * 16 + lr8 + radd) * 128 + cb)), bf[n2]);
#pragma unroll
                for (int ni = 0; ni < 8; ni++)
                    mma_f16(s[ni], qa[kk], bf[ni >> 1][ni & 1], bf[ni >> 1][(ni & 1) + 2]);
            }

            // causal mask (tiles overlapping this warp's diagonal)
            if (kt * 64 + 63 > qt * 128 + warp * 16) {
#pragma unroll
                for (int f = 0; f < 8; f++)
#pragma unroll
                    for (int j = 0; j < 4; j++) {
                        int kc = kt * 64 + f * 8 + (lane & 3) * 2 + (j & 1);
                        int rr = rq0 + ((j >= 2) ? 8 : 0);
                        if (kc > rr) s[f][j] = -1e30f;
                    }
            }

            float tm0 = -1e30f, tm1 = -1e30f;
#pragma unroll
            for (int f = 0; f < 8; f++) {
                tm0 = fmaxf(tm0, fmaxf(s[f][0], s[f][1]));
                tm1 = fmaxf(tm1, fmaxf(s[f][2], s[f][3]));
            }
            tm0 = fmaxf(tm0, __shfl_xor_sync(0xffffffffu, tm0, 1));
            tm0 = fmaxf(tm0, __shfl_xor_sync(0xffffffffu, tm0, 2));
            tm1 = fmaxf(tm1, __shfl_xor_sync(0xffffffffu, tm1, 1));
            tm1 = fmaxf(tm1, __shfl_xor_sync(0xffffffffu, tm1, 2));
            float nm0 = fmaxf(m0v, tm0), nm1 = fmaxf(m1v, tm1);
            float f0 = __expf(m0v - nm0), f1 = __expf(m1v - nm1);
            float ts0 = 0.f, ts1 = 0.f;
#pragma unroll
            for (int f = 0; f < 8; f++) {
                s[f][0] = __expf(s[f][0] - nm0);
                s[f][1] = __expf(s[f][1] - nm0);
                s[f][2] = __expf(s[f][2] - nm1);
                s[f][3] = __expf(s[f][3] - nm1);
                ts0 += s[f][0] + s[f][1];
                ts1 += s[f][2] + s[f][3];
            }
            ts0 += __shfl_xor_sync(0xffffffffu, ts0, 1);
            ts0 += __shfl_xor_sync(0xffffffffu, ts0, 2);
            ts1 += __shfl_xor_sync(0xffffffffu, ts1, 1);
            ts1 += __shfl_xor_sync(0xffffffffu, ts1, 2);
            l0 = l0 * f0 + ts0; l1 = l1 * f1 + ts1;
            m0v = nm0; m1v = nm1;
#pragma unroll
            for (int f = 0; f < 8; f++) {
                o[f][0] *= f0; o[f][1] *= f0; o[f][2] *= f1; o[f][3] *= f1;
            }

            uint32_t pa[4][4];
#pragma unroll
            for (int kk = 0; kk < 4; kk++) {
                pa[kk][0] = pk2h(s[2 * kk][0],     s[2 * kk][1]);
                pa[kk][1] = pk2h(s[2 * kk][2],     s[2 * kk][3]);
                pa[kk][2] = pk2h(s[2 * kk + 1][0], s[2 * kk + 1][1]);
                pa[kk][3] = pk2h(s[2 * kk + 1][2], s[2 * kk + 1][3]);
            }
#pragma unroll
            for (int kk = 0; kk < 4; kk++) {
                uint32_t vbf[4][4];
#pragma unroll
                for (int ng = 0; ng < 4; ng++)
                    ldsm4t(vs + swz((uint32_t)((kk * 16 + lr8 + radd) * 128 + ng * 32 + cadd)), vbf[ng]);
#pragma unroll
                for (int ni = 0; ni < 8; ni++)
                    mma_f16(o[ni], pa[kk], vbf[ni >> 1][(ni & 1) * 2], vbf[ni >> 1][(ni & 1) * 2 + 1]);
            }
        }
        __syncthreads();   // stage consumed (all warps) before overwrite
    }

    float il0 = 1.f / l0, il1 = 1.f / l1;
    const int row0 = b * SS + rq0;
#pragma unroll
    for (int f = 0; f < 8; f++) {
        int col = h * 64 + f * 8 + (lane & 3) * 2;
        float v0 = o[f][0] * il0, v1 = o[f][1] * il0;
        float v2 = o[f][2] * il1, v3 = o[f][3] * il1;
        __half h0 = __float2half_rn(v0), h1 = __float2half_rn(v1);
        __half h2 = __float2half_rn(v2), h3 = __float2half_rn(v3);
        size_t p0 = (size_t)row0 * DD + col;
        size_t p1 = (size_t)(row0 + 8) * DD + col;
        *(uint32_t*)(oh + p0) = (uint32_t)__half_as_ushort(h0) | ((uint32_t)__half_as_ushort(h1) << 16);
        *(uint32_t*)(ol + p0) = pk2h(v0 - __half2float(h0), v1 - __half2float(h1));
        *(uint32_t*)(oh + p1) = (uint32_t)__half_as_ushort(h2) | ((uint32_t)__half_as_ushort(h3) << 16);
        *(uint32_t*)(ol + p1) = pk2h(v2 - __half2float(h2), v3 - __half2float(h3));
    }
}

// ---------------- launch ----------------
extern "C" void kernel_launch(void* const* d_in, const int* in_sizes, int n_in,
                              void* d_out, int out_size)
{
    const int*   idx     = (const int*)d_in[0];
    const float* tok_emb = (const float*)d_in[1];
    const float* pos_emb = (const float*)d_in[2];
    const float* qkv_w   = (const float*)d_in[3];
    const float* proj_w  = (const float*)d_in[4];
    const float* proj_b  = (const float*)d_in[5];
    const float* ln1_g   = (const float*)d_in[6];
    const float* ln1_b   = (const float*)d_in[7];
    const float* ln2_g   = (const float*)d_in[8];
    const float* ln2_b   = (const float*)d_in[9];
    const float* w1      = (const float*)d_in[10];
    const float* b1      = (const float*)d_in[11];
    const float* w2      = (const float*)d_in[12];
    const float* b2      = (const float*)d_in[13];
    const float* lnf_g   = (const float*)d_in[14];
    const float* lnf_b   = (const float*)d_in[15];
    const float* head_w  = (const float*)d_in[16];
    const float* head_b  = (const float*)d_in[17];
    float* out = (float*)d_out;

    float* x;
    __half *qkvh, *lnh, *lnl, *ah, *al, *ffh, *ffl, *w;
    cudaGetSymbolAddress((void**)&x, g_x);
    cudaGetSymbolAddress((void**)&qkvh, g_qkvh);
    cudaGetSymbolAddress((void**)&lnh, g_lnh);
    cudaGetSymbolAddress((void**)&lnl, g_lnl);
    cudaGetSymbolAddress((void**)&ah, g_ah);
    cudaGetSymbolAddress((void**)&al, g_al);
    cudaGetSymbolAddress((void**)&ffh, g_ffh);
    cudaGetSymbolAddress((void**)&ffl, g_ffl);
    cudaGetSymbolAddress((void**)&w, g_w);

    cudaFuncSetAttribute(gemm_tc, cudaFuncAttributeMaxDynamicSharedMemorySize, SMEM_GEMM);

    // round all weights to single fp16 (one fused launch)
    split_all_kernel<<<(TOTW / 4 + 255) / 256, 256>>>(
        (const float4*)qkv_w, (const float4*)proj_w, (const float4*)w1,
        (const float4*)w2, (const float4*)head_w, (uint2*)w);

    embed_kernel<<<NTOK, 256>>>(idx, tok_emb, pos_emb, x);

    for (int l = 0; l < LL; l++) {
        // ln1 -> qkv (fp16 out for attention)
        ln_kernel<<<NTOK, 256>>>(x, ln1_g + l * DD, ln1_b + l * DD, lnh, lnl);
        gemm_tc<<<dim3(32, 24), 256, SMEM_GEMM>>>(
            lnh, lnl, w + OFF_QKV + (size_t)l * 3 * DD * DD,
            nullptr, nullptr, nullptr, qkvh, nullptr, nullptr, NTOK, 3 * DD, DD, 0);
        // attention (HMMA flash, 128-query CTAs) -> split fp16 output
        attn_hmma<<<dim3(SS / 128, HH, BB), 256>>>(qkvh, ah, al);
        // proj + residual (fp32 x)
        gemm_tc<<<dim3(32, 8), 256, SMEM_GEMM>>>(
            ah, al, w + OFF_PROJ + (size_t)l * DD * DD,
            proj_b + l * DD, x, x, nullptr, nullptr, nullptr, NTOK, DD, DD, 0);
        // ln2 -> MLP
        ln_kernel<<<NTOK, 256>>>(x, ln2_g + l * DD, ln2_b + l * DD, lnh, lnl);
        gemm_tc<<<dim3(32, 32), 256, SMEM_GEMM>>>(
            lnh, lnl, w + OFF_W1 + (size_t)l * FF_DIM * DD,
            b1 + l * FF_DIM, nullptr, nullptr, nullptr, ffh, ffl, NTOK, FF_DIM, DD, 1);
        gemm_tc<<<dim3(32, 8), 256, SMEM_GEMM>>>(
            ffh, ffl, w + OFF_W2 + (size_t)l * DD * FF_DIM,
            b2 + l * DD, x, x, nullptr, nullptr, nullptr, NTOK, DD, FF_DIM, 0);
    }

    // final LN + LM head
    ln_kernel<<<NTOK, 256>>>(x, lnf_g, lnf_b, lnh, lnl);
    gemm_tc<<<dim3(32, VV / 128), 256, SMEM_GEMM>>>(
        lnh, lnl, w + OFF_HEAD,
        head_b, nullptr, out, nullptr, nullptr, nullptr, NTOK, VV, DD, 0);
}